// round 17
// baseline (speedup 1.0000x reference)
#include <cuda_runtime.h>
#include <cstdint>

// Problem constants (fixed by the reference).
#define B_  4
#define T_  2048
#define D_  1024
#define H_  16
#define DH_ 64
#define M_  (B_*T_)   // 8192

// Scratch (device globals: no cudaMalloc allowed).
__device__ uint16_t g_Aq [(size_t)M_*D_];      // fp16 inputs q,k,v
__device__ uint16_t g_Ak [(size_t)M_*D_];
__device__ uint16_t g_Av [(size_t)M_*D_];
__device__ uint16_t g_Wq [(size_t)D_*D_];      // fp16 weights
__device__ uint16_t g_Wk [(size_t)D_*D_];
__device__ uint16_t g_Wv [(size_t)D_*D_];
__device__ uint16_t g_Qh [(size_t)M_*D_];      // [B,H,T,DH] fp16 projections
__device__ uint16_t g_Kh [(size_t)M_*D_];
__device__ uint16_t g_Vh [(size_t)M_*D_];
__device__ uint32_t g_Vp [(size_t)M_*D_/2];    // [B,H,DH,T/2] fp16-pairs
__device__ uint16_t g_Ao [(size_t)M_*D_];      // flash out fp16 [M,D]
__device__ uint16_t g_Wo [(size_t)D_*D_];      // wo fp16

// ---------------------------------------------------------------------------
// Helpers
// ---------------------------------------------------------------------------
__device__ __forceinline__ uint32_t smem_u32(const void* p) {
    uint32_t a;
    asm("{ .reg .u64 t; cvta.to.shared.u64 t, %1; cvt.u32.u64 %0, t; }"
        : "=r"(a) : "l"(p));
    return a;
}
__device__ __forceinline__ float ex2f(float x) {
    float r;
    asm("ex2.approx.f32 %0, %1;" : "=f"(r) : "f"(x));
    return r;
}
__device__ __forceinline__ uint32_t f16x2_of(float lo, float hi) {
    uint32_t r;
    asm("cvt.rn.f16x2.f32 %0, %1, %2;" : "=r"(r) : "f"(hi), "f"(lo));
    return r;
}
__device__ __forceinline__ void mma16816(float* c, const uint32_t* a,
                                         uint32_t b0, uint32_t b1) {
    asm volatile(
        "mma.sync.aligned.m16n8k16.row.col.f32.f16.f16.f32 "
        "{%0,%1,%2,%3}, {%4,%5,%6,%7}, {%8,%9}, {%0,%1,%2,%3};"
        : "+f"(c[0]), "+f"(c[1]), "+f"(c[2]), "+f"(c[3])
        : "r"(a[0]), "r"(a[1]), "r"(a[2]), "r"(a[3]), "r"(b0), "r"(b1));
}
#define LDSM4(r, a) \
    asm volatile("ldmatrix.sync.aligned.m8n8.x4.shared.b16 {%0,%1,%2,%3}, [%4];" \
        : "=r"((r)[0]), "=r"((r)[1]), "=r"((r)[2]), "=r"((r)[3]) : "r"(a))
#define CP16(dst, src) \
    asm volatile("cp.async.cg.shared.global [%0], [%1], 16;" :: "r"(dst), "l"(src))
#define CP_COMMIT() asm volatile("cp.async.commit_group;" ::: "memory")
#define CP_WAIT0()  asm volatile("cp.async.wait_group 0;" ::: "memory")
#define CP_WAIT1()  asm volatile("cp.async.wait_group 1;" ::: "memory")

// ---------------------------------------------------------------------------
// Prepass: convert three fp32 arrays to fp16 in one launch (y selects).
// ---------------------------------------------------------------------------
__global__ void __launch_bounds__(256) cvt3(
    const float4* __restrict__ s0, const float4* __restrict__ s1,
    const float4* __restrict__ s2,
    uint4* __restrict__ d0, uint4* __restrict__ d1, uint4* __restrict__ d2,
    int n8)
{
    const float4* s = (blockIdx.y == 0) ? s0 : (blockIdx.y == 1) ? s1 : s2;
    uint4* d = (blockIdx.y == 0) ? d0 : (blockIdx.y == 1) ? d1 : d2;
    for (int i = blockIdx.x * 256 + threadIdx.x; i < n8; i += gridDim.x * 256) {
        float4 a0 = s[2*i], a1 = s[2*i+1];
        uint4 o;
        o.x = f16x2_of(a0.x, a0.y);
        o.y = f16x2_of(a0.z, a0.w);
        o.z = f16x2_of(a1.x, a1.y);
        o.w = f16x2_of(a1.z, a1.w);
        d[i] = o;
    }
}
__global__ void __launch_bounds__(256) cvt1(
    const float4* __restrict__ s, uint4* __restrict__ d, int n8)
{
    for (int i = blockIdx.x * 256 + threadIdx.x; i < n8; i += gridDim.x * 256) {
        float4 a0 = s[2*i], a1 = s[2*i+1];
        uint4 o;
        o.x = f16x2_of(a0.x, a0.y);
        o.y = f16x2_of(a0.z, a0.w);
        o.z = f16x2_of(a1.x, a1.y);
        o.w = f16x2_of(a1.z, a1.w);
        d[i] = o;
    }
}

// ---------------------------------------------------------------------------
// HMMA GEMM core (validated R14/R15), 3-stage cp.async ring.
// ---------------------------------------------------------------------------
#define GS_ROWB  80
#define GS_SLAB  (128*GS_ROWB)     // 10240
#define GS_A     0
#define GS_W     GS_SLAB
#define GS_STAGE (2*GS_SLAB)       // 20480
#define GS_SMEM  (3*GS_STAGE)      // 61440

#define GEMM_PROLOG()                                                           \
    extern __shared__ char smem[];                                              \
    const uint32_t sb = smem_u32(smem);                                         \
    const int tid  = threadIdx.x;                                               \
    const int wid  = tid >> 5;                                                  \
    const int lane = tid & 31;                                                  \
    const int g    = lane >> 2;                                                 \
    const int tg   = lane & 3;                                                  \
    const int wm   = wid & 3;                                                   \
    const int wn   = wid >> 2;                                                  \
    const int bm = blockIdx.x << 7;                                             \
    const int bn = blockIdx.y << 7;                                             \
    const int crow0 = tid >> 2;                                                 \
    const int cq    = (tid & 3) << 4;                                           \
    const int ck    = (tid & 3) << 3;                                           \
    float acc[2][8][4];                                                         \
    _Pragma("unroll")                                                           \
    for (int mt = 0; mt < 2; mt++)                                              \
        _Pragma("unroll")                                                       \
        for (int nt = 0; nt < 8; nt++)                                          \
            _Pragma("unroll")                                                   \
            for (int c = 0; c < 4; c++) acc[mt][nt][c] = 0.f;

#define ISSUE_CHUNK(kc, s) do {                                                 \
    const int k0_ = (kc) * 32;                                                  \
    const uint32_t st_ = sb + (s) * GS_STAGE;                                   \
    _Pragma("unroll")                                                           \
    for (int rr = 0; rr < 2; rr++) {                                            \
        const int row_ = crow0 + rr * 64;                                       \
        const uint32_t so_ = st_ + row_ * GS_ROWB + cq;                         \
        const size_t ga_ = (size_t)(bm + row_) * D_ + k0_ + ck;                 \
        const size_t gw_ = (size_t)(bn + row_) * D_ + k0_ + ck;                 \
        CP16(so_ + GS_A, Ah + ga_);                                             \
        CP16(so_ + GS_W, Wh + gw_);                                             \
    }                                                                           \
    CP_COMMIT();                                                                \
} while (0)

// 3-stage ring: issue kc and kc+1 up front; in-loop issue kc+2 (or empty
// commit to keep the FIFO group count aligned so wait_group 1 proves the
// current chunk has landed).
#define GEMM_MAINLOOP()                                                         \
    ISSUE_CHUNK(0, 0);                                                          \
    ISSUE_CHUNK(1, 1);                                                          \
    const uint32_t fr_a = (uint32_t)((wm*32 + (lane & 15)) * GS_ROWB + ((lane >> 4) << 4)); \
    const uint32_t fr_b = (uint32_t)((wn*64 + (lane & 15)) * GS_ROWB + ((lane >> 4) << 4)); \
    int rs_ = 0, ws_ = 2;                                                       \
    for (int kc = 0; kc < 32; kc++) {                                           \
        const uint32_t st = sb + rs_ * GS_STAGE;                                \
        CP_WAIT1();                                                             \
        __syncthreads();                                                        \
        if (kc + 2 < 32) { ISSUE_CHUNK(kc + 2, ws_); } else { CP_COMMIT(); }    \
        ws_ = (ws_ == 2) ? 0 : ws_ + 1;                                         \
        rs_ = (rs_ == 2) ? 0 : rs_ + 1;                                         \
        _Pragma("unroll")                                                       \
        for (int k16 = 0; k16 < 2; k16++) {                                     \
            const uint32_t ko = k16 * 32;                                       \
            uint32_t ah[2][4];                                                  \
            _Pragma("unroll")                                                   \
            for (int mt = 0; mt < 2; mt++)                                      \
                LDSM4(ah[mt], st + GS_A + fr_a + mt*(16*GS_ROWB) + ko);         \
            _Pragma("unroll")                                                   \
            for (int ntp = 0; ntp < 4; ntp++) {                                 \
                uint32_t bh[4];                                                 \
                LDSM4(bh, st + GS_W + fr_b + ntp*(16*GS_ROWB) + ko);            \
                _Pragma("unroll")                                               \
                for (int mt = 0; mt < 2; mt++) {                                \
                    mma16816(acc[mt][2*ntp],   ah[mt], bh[0], bh[2]);           \
                    mma16816(acc[mt][2*ntp+1], ah[mt], bh[1], bh[3]);           \
                }                                                               \
            }                                                                   \
        }                                                                       \
    }

// Batched QKV projection: grid (64, 8, 3). Scatter fp16 to [B,H,T,DH].
__global__ void __launch_bounds__(256) gemm_qkv(
    const uint16_t* __restrict__ A0, const uint16_t* __restrict__ A1,
    const uint16_t* __restrict__ A2,
    const uint16_t* __restrict__ W0, const uint16_t* __restrict__ W1,
    const uint16_t* __restrict__ W2,
    const float* __restrict__ b0v, const float* __restrict__ b1v,
    const float* __restrict__ b2v,
    uint16_t* __restrict__ O0, uint16_t* __restrict__ O1,
    uint16_t* __restrict__ O2, float qscale)
{
    const int z = blockIdx.z;
    const uint16_t* Ah = (z == 0) ? A0 : (z == 1) ? A1 : A2;
    const uint16_t* Wh = (z == 0) ? W0 : (z == 1) ? W1 : W2;
    const float* bias  = (z == 0) ? b0v : (z == 1) ? b1v : b2v;
    uint16_t* Oh       = (z == 0) ? O0 : (z == 1) ? O1 : O2;
    const float scale  = (z == 0) ? qscale : 1.0f;

    GEMM_PROLOG();
    GEMM_MAINLOOP();

    #pragma unroll
    for (int mt = 0; mt < 2; mt++) {
        const int rg = bm + wm*32 + mt*16 + g;
        #pragma unroll
        for (int nt = 0; nt < 8; nt++) {
            const int col = bn + wn*64 + nt*8 + tg*2;
            float2 bv = *(const float2*)(bias + col);
            float v0 = (acc[mt][nt][0] + bv.x) * scale;
            float v1 = (acc[mt][nt][1] + bv.y) * scale;
            float v2 = (acc[mt][nt][2] + bv.x) * scale;
            float v3 = (acc[mt][nt][3] + bv.y) * scale;
            const int b  = rg >> 11;
            const int t0 = rg & (T_ - 1);
            const int hh = col >> 6;
            const int d0 = col & 63;
            size_t idx = ((((size_t)(b*H_ + hh)) * T_ + t0) * DH_ + d0) >> 1;
            ((uint32_t*)Oh)[idx]       = f16x2_of(v0, v1);
            ((uint32_t*)Oh)[idx + 256] = f16x2_of(v2, v3);   // rows +8
        }
    }
}

// Output projection: fp32 out [M,D].
__global__ void __launch_bounds__(256) gemm_out(
    const uint16_t* __restrict__ Ah, const uint16_t* __restrict__ Wh,
    const float* __restrict__ bias, float* __restrict__ C)
{
    GEMM_PROLOG();
    GEMM_MAINLOOP();

    #pragma unroll
    for (int mt = 0; mt < 2; mt++) {
        const int rg = bm + wm*32 + mt*16 + g;
        #pragma unroll
        for (int nt = 0; nt < 8; nt++) {
            const int col = bn + wn*64 + nt*8 + tg*2;
            float2 bv = *(const float2*)(bias + col);
            *(float2*)(C + (size_t)rg * D_ + col) =
                make_float2(acc[mt][nt][0] + bv.x, acc[mt][nt][1] + bv.y);
            *(float2*)(C + (size_t)(rg + 8) * D_ + col) =
                make_float2(acc[mt][nt][2] + bv.x, acc[mt][nt][3] + bv.y);
        }
    }
}

// ---------------------------------------------------------------------------
// V transpose: [B,H,T,DH] fp16 -> [B,H,DH,T/2] fp16-pair uint32.
// ---------------------------------------------------------------------------
__global__ void __launch_bounds__(128) vtrans(
    const uint16_t* __restrict__ Vh, uint32_t* __restrict__ Vp)
{
    __shared__ uint16_t sm[64*72];   // pitch 72 u16 = 144B
    const int tid = threadIdx.x;
    const int tb = blockIdx.x;
    const int h = blockIdx.y, b = blockIdx.z;
    const size_t base = (size_t)(b*H_ + h) * T_ * DH_;
    #pragma unroll
    for (int i = 0; i < 4; i++) {
        int c = tid + i*128;
        int row = c >> 3, c16 = c & 7;
        uint4 vh = *(const uint4*)(Vh + base + (size_t)(tb*64 + row)*DH_ + c16*8);
        *(uint4*)&sm[row*72 + c16*8] = vh;
    }
    __syncthreads();
    const size_t obase = (size_t)(b*H_ + h) * DH_ * (T_/2) + tb*32;
    #pragma unroll
    for (int i = 0; i < 4; i++) {
        int c = tid + i*128;
        int d = c >> 3, q4 = c & 7;
        uint32_t w[4];
        #pragma unroll
        for (int p = 0; p < 4; p++) {
            int t = q4*8 + p*2;
            w[p] = (uint32_t)sm[t*72 + d] | ((uint32_t)sm[(t+1)*72 + d] << 16);
        }
        *(uint4*)(Vp + obase + (size_t)d*(T_/2) + q4*4) = make_uint4(w[0],w[1],w[2],w[3]);
    }
}

// ---------------------------------------------------------------------------
// Flash attention, HMMA fp16 (causal), BC=128, 3-stage cp.async ring.
// Block = (b,h,128 q-rows), 256 thr / 8 warps (warp = m16 rows). Q fragments
// in regs; K pitch 144B, Vp pitch 272B (both LDSM conflict-free).
// S-fragment reused as PV A-fragment. Writes fp16 [M,D].
// ---------------------------------------------------------------------------
#define FK_ROWB  144
#define FV_ROWB  272
#define FK_BYTES (128*FK_ROWB)    // 18432
#define FV_BYTES (64*FV_ROWB)     // 17408
#define FB_STAGE (FK_BYTES + FV_BYTES)  // 35840
#define FB_SMEM  (3*FB_STAGE)     // 107520

__global__ void __launch_bounds__(256, 1) flash_mma(
    const uint16_t* __restrict__ Qh, const uint16_t* __restrict__ Kh,
    const uint32_t* __restrict__ Vp, uint16_t* __restrict__ Ao)
{
    extern __shared__ char smem[];
    const uint32_t sb = smem_u32(smem);
    const int tid = threadIdx.x;
    const int wid = tid >> 5;
    const int lane = tid & 31;
    const int g = lane >> 2, tg = lane & 3;

    const int qb = (int)(gridDim.x - 1u - blockIdx.x);  // long blocks first
    const int h = blockIdx.y, b = blockIdx.z;
    const size_t qkb = (size_t)(b*H_ + h) * T_ * DH_;
    const size_t vpb = (size_t)(b*H_ + h) * DH_ * (T_/2);

    // ---- stage Q tile (128 rows x 128B @144 pitch), hoist to regs ----
    #pragma unroll
    for (int i = 0; i < 4; i++) {
        int c = tid + i*256;              // 1024 16B chunks
        int row = c >> 3, c16 = c & 7;
        uint32_t dst = sb + row*FK_ROWB + c16*16;
        CP16(dst, Qh + qkb + (size_t)(qb*128 + row)*DH_ + c16*8);
    }
    CP_COMMIT(); CP_WAIT0();
    __syncthreads();

    uint32_t qh[4][4];
    {
        const uint32_t fra = sb + (uint32_t)((wid*16 + (lane & 15))*FK_ROWB + ((lane >> 4) << 4));
        #pragma unroll
        for (int kk = 0; kk < 4; kk++)
            LDSM4(qh[kk], fra + kk*32);
    }
    __syncthreads();

    float o[8][4];
    #pragma unroll
    for (int nt = 0; nt < 8; nt++)
        #pragma unroll
        for (int c = 0; c < 4; c++) o[nt][c] = 0.f;
    float m0 = -1e30f, m1 = -1e30f, l0 = 0.f, l1 = 0.f;

    #define FB_ISSUE(kb, s) do {                                                \
        const uint32_t stb_ = sb + (s) * FB_STAGE;                              \
        _Pragma("unroll")                                                       \
        for (int i_ = 0; i_ < 4; i_++) {                                        \
            int cc_ = tid + i_*256;                                             \
            int krow_ = cc_ >> 3, kc16_ = cc_ & 7;                              \
            CP16(stb_ + krow_*FK_ROWB + kc16_*16,                               \
                 Kh + qkb + (size_t)((kb)*128 + krow_)*DH_ + kc16_*8);          \
            int vrow_ = cc_ >> 4, vc16_ = cc_ & 15;                             \
            CP16(stb_ + FK_BYTES + vrow_*FV_ROWB + vc16_*16,                    \
                 Vp + vpb + (size_t)vrow_*(T_/2) + (kb)*64 + vc16_*4);          \
        }                                                                       \
        CP_COMMIT();                                                            \
    } while (0)

    const int kbmax = qb;            // causal: 128-key blocks 0..qb
    FB_ISSUE(0, 0);
    if (kbmax >= 1) { FB_ISSUE(1, 1); } else { CP_COMMIT(); }
    int rs = 0, ws = 2;

    for (int kb = 0; kb <= kbmax; kb++) {
        const uint32_t st = sb + (uint32_t)(rs * FB_STAGE);
        CP_WAIT1();
        __syncthreads();
        if (kb + 2 <= kbmax) { FB_ISSUE(kb + 2, ws); } else { CP_COMMIT(); }
        ws = (ws == 2) ? 0 : ws + 1;
        rs = (rs == 2) ? 0 : rs + 1;

        const uint32_t frbK = st + (uint32_t)((lane & 15)*FK_ROWB + ((lane >> 4) << 4));
        const uint32_t frbV = st + FK_BYTES + (uint32_t)((lane & 15)*FV_ROWB + ((lane >> 4) << 4));

        // ---- S = Q K^T (128 q x 128 k per block; 16 n8 tiles) ----
        float s[16][4];
        #pragma unroll
        for (int nt = 0; nt < 16; nt++)
            #pragma unroll
            for (int c = 0; c < 4; c++) s[nt][c] = 0.f;

        #pragma unroll
        for (int kk = 0; kk < 4; kk++) {
            #pragma unroll
            for (int ntp = 0; ntp < 8; ntp++) {
                uint32_t bh[4];
                LDSM4(bh, frbK + ntp*(16*FK_ROWB) + kk*32);
                mma16816(s[2*ntp],   qh[kk], bh[0], bh[2]);
                mma16816(s[2*ntp+1], qh[kk], bh[1], bh[3]);
            }
        }

        // ---- causal mask (diagonal tile only) ----
        if (kb == qb) {
            const int q0 = qb*128 + wid*16 + g;
            #pragma unroll
            for (int nt = 0; nt < 16; nt++) {
                int j0 = kb*128 + nt*8 + tg*2;
                if (j0     > q0)     s[nt][0] = -1e30f;
                if (j0 + 1 > q0)     s[nt][1] = -1e30f;
                if (j0     > q0 + 8) s[nt][2] = -1e30f;
                if (j0 + 1 > q0 + 8) s[nt][3] = -1e30f;
            }
        }

        // ---- online softmax (rows g, g+8; quad shuffles over tg) ----
        float mx0 = -1e30f, mx1 = -1e30f;
        #pragma unroll
        for (int nt = 0; nt < 16; nt++) {
            mx0 = fmaxf(mx0, fmaxf(s[nt][0], s[nt][1]));
            mx1 = fmaxf(mx1, fmaxf(s[nt][2], s[nt][3]));
        }
        mx0 = fmaxf(mx0, __shfl_xor_sync(0xffffffffu, mx0, 1));
        mx0 = fmaxf(mx0, __shfl_xor_sync(0xffffffffu, mx0, 2));
        mx1 = fmaxf(mx1, __shfl_xor_sync(0xffffffffu, mx1, 1));
        mx1 = fmaxf(mx1, __shfl_xor_sync(0xffffffffu, mx1, 2));
        float mn0 = fmaxf(m0, mx0), mn1 = fmaxf(m1, mx1);
        float a0 = ex2f(m0 - mn0), a1 = ex2f(m1 - mn1);
        m0 = mn0; m1 = mn1;
        float rs0 = 0.f, rs1 = 0.f;
        #pragma unroll
        for (int nt = 0; nt < 16; nt++) {
            s[nt][0] = ex2f(s[nt][0] - mn0); rs0 += s[nt][0];
            s[nt][1] = ex2f(s[nt][1] - mn0); rs0 += s[nt][1];
            s[nt][2] = ex2f(s[nt][2] - mn1); rs1 += s[nt][2];
            s[nt][3] = ex2f(s[nt][3] - mn1); rs1 += s[nt][3];
        }
        rs0 += __shfl_xor_sync(0xffffffffu, rs0, 1);
        rs0 += __shfl_xor_sync(0xffffffffu, rs0, 2);
        rs1 += __shfl_xor_sync(0xffffffffu, rs1, 1);
        rs1 += __shfl_xor_sync(0xffffffffu, rs1, 2);
        l0 = l0 * a0 + rs0;
        l1 = l1 * a1 + rs1;
        #pragma unroll
        for (int nt = 0; nt < 8; nt++) {
            o[nt][0] *= a0; o[nt][1] *= a0;
            o[nt][2] *= a1; o[nt][3] *= a1;
        }

        // ---- O += P V  (P packed per k-step from S fragments) ----
        #pragma unroll
        for (int kk = 0; kk < 8; kk++) {
            uint32_t ph[4];
            ph[0] = f16x2_of(s[2*kk][0],   s[2*kk][1]);
            ph[1] = f16x2_of(s[2*kk][2],   s[2*kk][3]);
            ph[2] = f16x2_of(s[2*kk+1][0], s[2*kk+1][1]);
            ph[3] = f16x2_of(s[2*kk+1][2], s[2*kk+1][3]);
            #pragma unroll
            for (int ntp = 0; ntp < 4; ntp++) {
                uint32_t vh[4];
                LDSM4(vh, frbV + ntp*(16*FV_ROWB) + kk*32);
                mma16816(o[2*ntp],   ph, vh[0], vh[2]);
                mma16816(o[2*ntp+1], ph, vh[1], vh[3]);
            }
        }
    }

    // ---- normalize + write fp16 AO [M, D] directly ----
    const float i0 = 1.f / l0, i1 = 1.f / l1;
    const int t0 = qb*128 + wid*16 + g;
    uint32_t* baseA = (uint32_t*)(Ao + ((size_t)b*T_ + t0)*D_ + h*DH_ + tg*2);
    #pragma unroll
    for (int nt = 0; nt < 8; nt++) {
        baseA[nt*4]              = f16x2_of(o[nt][0]*i0, o[nt][1]*i0);
        baseA[8*(D_/2) + nt*4]   = f16x2_of(o[nt][2]*i1, o[nt][3]*i1);
    }
}

// ---------------------------------------------------------------------------
// Host launcher.
// ---------------------------------------------------------------------------
extern "C" void kernel_launch(void* const* d_in, const int* in_sizes, int n_in,
                              void* d_out, int out_size)
{
    const float* q  = (const float*)d_in[0];
    const float* k  = (const float*)d_in[1];
    const float* v  = (const float*)d_in[2];
    const float* wq = (const float*)d_in[5];
    const float* bq = (const float*)d_in[6];
    const float* wk = (const float*)d_in[7];
    const float* bk = (const float*)d_in[8];
    const float* wv = (const float*)d_in[9];
    const float* bv = (const float*)d_in[10];
    const float* wo = (const float*)d_in[11];
    const float* bo = (const float*)d_in[12];
    float* out = (float*)d_out;

    uint16_t *Aq, *Ak, *Av, *Wq, *Wk, *Wv, *Qh, *Kh, *Vh, *Ao, *Wo;
    uint32_t *Vp;
    cudaGetSymbolAddress((void**)&Aq, g_Aq);
    cudaGetSymbolAddress((void**)&Ak, g_Ak);
    cudaGetSymbolAddress((void**)&Av, g_Av);
    cudaGetSymbolAddress((void**)&Wq, g_Wq);
    cudaGetSymbolAddress((void**)&Wk, g_Wk);
    cudaGetSymbolAddress((void**)&Wv, g_Wv);
    cudaGetSymbolAddress((void**)&Qh, g_Qh);
    cudaGetSymbolAddress((void**)&Kh, g_Kh);
    cudaGetSymbolAddress((void**)&Vh, g_Vh);
    cudaGetSymbolAddress((void**)&Vp, g_Vp);
    cudaGetSymbolAddress((void**)&Ao, g_Ao);
    cudaGetSymbolAddress((void**)&Wo, g_Wo);

    cudaFuncSetAttribute(gemm_qkv,
                         cudaFuncAttributeMaxDynamicSharedMemorySize, GS_SMEM);
    cudaFuncSetAttribute(gemm_out,
                         cudaFuncAttributeMaxDynamicSharedMemorySize, GS_SMEM);
    cudaFuncSetAttribute(flash_mma,
                         cudaFuncAttributeMaxDynamicSharedMemorySize, FB_SMEM);

    const int nA8 = (M_ * D_) / 8;
    const int nW8 = (D_ * D_) / 8;
    const float QSCALE = 0.125f * 1.4426950408889634f;

    // convert inputs + weights (batched)
    cvt3<<<dim3(1024, 3), 256>>>((const float4*)q, (const float4*)k,
                                 (const float4*)v,
                                 (uint4*)Aq, (uint4*)Ak, (uint4*)Av, nA8);
    cvt3<<<dim3(256, 3), 256>>>((const float4*)wq, (const float4*)wk,
                                (const float4*)wv,
                                (uint4*)Wq, (uint4*)Wk, (uint4*)Wv, nW8);
    cvt1<<<256, 256>>>((const float4*)wo, (uint4*)Wo, nW8);

    // batched Q/K/V projections
    gemm_qkv<<<dim3(M_/128, D_/128, 3), 256, GS_SMEM>>>(
        Aq, Ak, Av, Wq, Wk, Wv, bq, bk, bv, Qh, Kh, Vh, QSCALE);

    vtrans<<<dim3(T_/64, H_, B_), 128>>>(Vh, Vp);

    flash_mma<<<dim3(T_/128, H_, B_), 256, FB_SMEM>>>(Qh, Kh, Vp, Ao);

    gemm_out<<<dim3(M_/128, D_/128), 256, GS_SMEM>>>(Ao, Wo, bo, out);
}